// round 1
// baseline (speedup 1.0000x reference)
#include <cuda_runtime.h>
#include <cstdint>
#include <math.h>

#define NN   64
#define BB   32
#define EE   4032
#define FF   256
#define BIG_M  (BB*EE)    // 129024
#define NODE_M (BB*NN)    // 2048
#define BIG_CH  (BIG_M/64)   // 2016
#define NODE_CH (NODE_M/64)  // 32

// ---------------- scratch (device globals; no allocs) ----------------
__device__ float g_nodeA[NODE_M*FF];
__device__ float g_nodeB[NODE_M*FF];
__device__ float g_nodeC[NODE_M*FF];
__device__ float g_nodeD[NODE_M*FF];
__device__ float g_P[NODE_M*FF];
__device__ float g_Q[NODE_M*FF];
__device__ float g_S[NODE_M*FF];
__device__ float g_R[NODE_M*FF];
__device__ float g_inc[NODE_M*FF];
__device__ float g_bigA[(size_t)BIG_M*FF];
__device__ float g_bigB[(size_t)BIG_M*FF];
__device__ float g_psum[BIG_CH*FF];
__device__ float g_psq[BIG_CH*FF];
__device__ float g_scale[4*FF];
__device__ float g_shift[4*FF];
__device__ float g_wskip[FF*FF];
__device__ float g_dbias[FF];
__device__ float g_fcw2[2*FF];
__device__ float g_fcb2[2];

__device__ __forceinline__ float eluf(float x){ return x > 0.f ? x : expm1f(x); }

// ---------------- generic 64x64-tile GEMM over K=256 ----------------
// MA=0: A is a direct [M,256] matrix (optional per-feature input affine AFF)
// MA=1: A[r][k] = ELU(P[send(r)]+Q[recv(r)]) (node->edge gather, bias folded in P)
// SR  : epilogue adds S[send(r)][c] + R[recv(r)][c] + dbias[c] before activation
// STATS: write per-(rowblock,col) partial sum/sumsq (deterministic, no atomics)
template<int MA, bool AFF, bool BIAS, bool ELUF, bool STATS, bool SR>
__global__ __launch_bounds__(64) void gemm_k(
    const float* __restrict__ A, const float* __restrict__ P, const float* __restrict__ Q,
    const float* __restrict__ W, const float* __restrict__ bias,
    const float* __restrict__ aSc, const float* __restrict__ aSh,
    const float* __restrict__ Sg, const float* __restrict__ Rg, const float* __restrict__ db,
    float* __restrict__ C, float* __restrict__ pSum, float* __restrict__ pSq)
{
    __shared__ __align__(16) float As[16][68];
    __shared__ __align__(16) float Bs[16][68];
    __shared__ int sPO[64], sQO[64];
    __shared__ float rS[64][8], rQ2[64][8];

    const int tid = threadIdx.x;
    const int rowbase = blockIdx.x * 64;
    const int n0 = blockIdx.y * 64;

    if (MA==1 || SR) {
        if (tid < 64) {
            int gr  = rowbase + tid;
            int b   = gr / EE;
            int e   = gr - b*EE;
            int snd = e / 63;
            int jp  = e - snd*63;
            int rcv = jp + (jp >= snd ? 1 : 0);
            sPO[tid] = (b*NN + snd)*FF;
            sQO[tid] = (b*NN + rcv)*FF;
        }
        __syncthreads();
    }

    const int ty = tid >> 3, tx = tid & 7;
    float acc[8][8];
    #pragma unroll
    for (int i=0;i<8;i++)
        #pragma unroll
        for (int j=0;j<8;j++) acc[i][j]=0.f;

    for (int k0 = 0; k0 < FF; k0 += 16) {
        // A tile: 64 rows x 16 k, transposed into As[k][m]
        #pragma unroll
        for (int p=0;p<4;p++){
            int idx = p*64 + tid;
            int row = idx >> 2, kq = idx & 3;
            float4 v;
            if (MA==0){
                v = *(const float4*)(A + (size_t)(rowbase+row)*FF + k0 + kq*4);
                if (AFF){
                    const float4 sc = *(const float4*)(aSc + k0 + kq*4);
                    const float4 sh = *(const float4*)(aSh + k0 + kq*4);
                    v.x = fmaf(sc.x, v.x, sh.x);
                    v.y = fmaf(sc.y, v.y, sh.y);
                    v.z = fmaf(sc.z, v.z, sh.z);
                    v.w = fmaf(sc.w, v.w, sh.w);
                }
            } else {
                float4 a4 = *(const float4*)(P + sPO[row] + k0 + kq*4);
                float4 b4 = *(const float4*)(Q + sQO[row] + k0 + kq*4);
                v.x = eluf(a4.x + b4.x);
                v.y = eluf(a4.y + b4.y);
                v.z = eluf(a4.z + b4.z);
                v.w = eluf(a4.w + b4.w);
            }
            As[kq*4+0][row]=v.x; As[kq*4+1][row]=v.y;
            As[kq*4+2][row]=v.z; As[kq*4+3][row]=v.w;
        }
        // B tile: 16 k x 64 n
        #pragma unroll
        for (int p=0;p<4;p++){
            int idx = p*64 + tid;
            int kk = idx >> 4, nq = idx & 15;
            *(float4*)&Bs[kk][nq*4] = *(const float4*)(W + (size_t)(k0+kk)*FF + n0 + nq*4);
        }
        __syncthreads();
        #pragma unroll
        for (int k=0;k<16;k++){
            float a0[8], b0[8];
            *(float4*)&a0[0] = *(float4*)&As[k][ty*8];
            *(float4*)&a0[4] = *(float4*)&As[k][ty*8+4];
            *(float4*)&b0[0] = *(float4*)&Bs[k][tx*8];
            *(float4*)&b0[4] = *(float4*)&Bs[k][tx*8+4];
            #pragma unroll
            for (int i=0;i<8;i++)
                #pragma unroll
                for (int j=0;j<8;j++)
                    acc[i][j] = fmaf(a0[i], b0[j], acc[i][j]);
        }
        __syncthreads();
    }

    // epilogue
    #pragma unroll
    for (int i=0;i<8;i++){
        int lrow = ty*8+i;
        int grow = rowbase + lrow;
        #pragma unroll
        for (int j=0;j<8;j++){
            int col = n0 + tx*8 + j;
            float v = acc[i][j];
            if (BIAS) v += bias[col];
            if (SR)   v += Sg[sPO[lrow] + col] + Rg[sQO[lrow] + col] + db[col];
            if (ELUF) v = eluf(v);
            acc[i][j] = v;
        }
        float* cp = C + (size_t)grow*FF + n0 + tx*8;
        *(float4*)cp     = make_float4(acc[i][0],acc[i][1],acc[i][2],acc[i][3]);
        *(float4*)(cp+4) = make_float4(acc[i][4],acc[i][5],acc[i][6],acc[i][7]);
    }

    if (STATS){
        #pragma unroll
        for (int j=0;j<8;j++){
            float s=0.f,q=0.f;
            #pragma unroll
            for (int i=0;i<8;i++){ float v=acc[i][j]; s+=v; q=fmaf(v,v,q); }
            rS[tid][j]=s; rQ2[tid][j]=q;
        }
        __syncthreads();
        if (tid < 64){
            int ctx = tid>>3, cj = tid&7;
            float s=0.f,q=0.f;
            #pragma unroll
            for (int t=0;t<8;t++){ s += rS[t*8+ctx][cj]; q += rQ2[t*8+ctx][cj]; }
            pSum[(size_t)blockIdx.x*FF + n0 + tid] = s;
            pSq [(size_t)blockIdx.x*FF + n0 + tid] = q;
        }
    }
}

// ---------------- small kernels ----------------
__global__ void finalize_bn(const float* __restrict__ pSum, const float* __restrict__ pSq,
                            int nchunks, const float* __restrict__ g, const float* __restrict__ beta,
                            float invM, float* __restrict__ sc, float* __restrict__ sh)
{
    int f = threadIdx.x;
    float s=0.f,q=0.f;
    for (int c=0;c<nchunks;c++){ s += pSum[(size_t)c*FF+f]; q += pSq[(size_t)c*FF+f]; }
    float mean = s*invM;
    float var  = fmaf(-mean, mean, q*invM);
    float a = g[f]*rsqrtf(var + 1e-5f);
    sc[f]=a; sh[f] = fmaf(-mean, a, beta[f]);
}

__global__ void edge2node_k(const float* __restrict__ h2, const float* __restrict__ sc,
                            const float* __restrict__ sh, float* __restrict__ inc)
{
    int bn = blockIdx.x; int b = bn >> 6; int n = bn & 63; int f = threadIdx.x;
    const float* base = h2 + (size_t)b*EE*FF + f;
    float s = 0.f;
    #pragma unroll
    for (int j=0;j<NN;j++){
        if (j==n) continue;
        int e = j*63 + (j < n ? n-1 : n);
        s += base[(size_t)e*FF];
    }
    inc[(size_t)bn*FF+f] = (sc[f]*s + 63.f*sh[f]) * (1.f/64.f);
}

__global__ void fold_skip_k(const float* __restrict__ w1, const float* __restrict__ sc2,
                            float* __restrict__ wsk)
{
    int f = blockIdx.x, c = threadIdx.x;
    wsk[f*FF+c] = sc2[f]*w1[(512+f)*FF + c];
}

__global__ void fold_dbias_k(const float* __restrict__ w1, const float* __restrict__ b1,
                             const float* __restrict__ sh2, float* __restrict__ db)
{
    int c = threadIdx.x;
    float s = b1[c];
    for (int f=0; f<FF; f++) s = fmaf(sh2[f], w1[(512+f)*FF + c], s);
    db[c]=s;
}

__global__ void fold_fc_k(const float* __restrict__ fcw, const float* __restrict__ fcb,
                          const float* __restrict__ sc, const float* __restrict__ sh,
                          float* __restrict__ fcw2, float* __restrict__ fcb2)
{
    int t = threadIdx.x;
    fcw2[2*t]   = sc[t]*fcw[2*t];
    fcw2[2*t+1] = sc[t]*fcw[2*t+1];
    if (t < 2){
        float s = fcb[t];
        for (int f=0; f<FF; f++) s = fmaf(sh[f], fcw[2*f+t], s);
        fcb2[t]=s;
    }
}

__global__ void final_out_k(const float* __restrict__ h4, const float* __restrict__ fcw2,
                            const float* __restrict__ fcb2, float* __restrict__ out)
{
    int warpId = threadIdx.x >> 5; int lane = threadIdx.x & 31;
    int row = blockIdx.x*8 + warpId;
    const float* hr = h4 + (size_t)row*FF;
    float s0=0.f, s1=0.f;
    #pragma unroll
    for (int f=lane; f<FF; f+=32){
        float h = hr[f];
        s0 = fmaf(h, fcw2[2*f],   s0);
        s1 = fmaf(h, fcw2[2*f+1], s1);
    }
    #pragma unroll
    for (int o=16;o;o>>=1){
        s0 += __shfl_down_sync(0xffffffffu, s0, o);
        s1 += __shfl_down_sync(0xffffffffu, s1, o);
    }
    if (lane==0){ out[(size_t)row*2]=s0+fcb2[0]; out[(size_t)row*2+1]=s1+fcb2[1]; }
}

// ---------------- host ----------------
extern "C" void kernel_launch(void* const* d_in, const int* in_sizes, int n_in,
                              void* d_out, int out_size)
{
    (void)in_sizes; (void)n_in; (void)out_size;
    const float* inputs = (const float*)d_in[0];
    const float* m1w1=(const float*)d_in[3],  *m1b1=(const float*)d_in[4],
               * m1w2=(const float*)d_in[5],  *m1b2=(const float*)d_in[6],
               * m1g =(const float*)d_in[7],  *m1be=(const float*)d_in[8];
    const float* m2w1=(const float*)d_in[9],  *m2b1=(const float*)d_in[10],
               * m2w2=(const float*)d_in[11], *m2b2=(const float*)d_in[12],
               * m2g =(const float*)d_in[13], *m2be=(const float*)d_in[14];
    const float* m3w1=(const float*)d_in[15], *m3b1=(const float*)d_in[16],
               * m3w2=(const float*)d_in[17], *m3b2=(const float*)d_in[18],
               * m3g =(const float*)d_in[19], *m3be=(const float*)d_in[20];
    const float* m4w1=(const float*)d_in[21], *m4b1=(const float*)d_in[22],
               * m4w2=(const float*)d_in[23], *m4b2=(const float*)d_in[24],
               * m4g =(const float*)d_in[25], *m4be=(const float*)d_in[26];
    const float* fcw =(const float*)d_in[27], *fcb =(const float*)d_in[28];
    float* out = (float*)d_out;

    float *nodeA,*nodeB,*nodeC,*nodeD,*P,*Q,*S,*R,*inc,*bigA,*bigB;
    float *psum,*psq,*scale,*shift,*wsk,*db,*fcw2,*fcb2;
    cudaGetSymbolAddress((void**)&nodeA, g_nodeA);
    cudaGetSymbolAddress((void**)&nodeB, g_nodeB);
    cudaGetSymbolAddress((void**)&nodeC, g_nodeC);
    cudaGetSymbolAddress((void**)&nodeD, g_nodeD);
    cudaGetSymbolAddress((void**)&P,     g_P);
    cudaGetSymbolAddress((void**)&Q,     g_Q);
    cudaGetSymbolAddress((void**)&S,     g_S);
    cudaGetSymbolAddress((void**)&R,     g_R);
    cudaGetSymbolAddress((void**)&inc,   g_inc);
    cudaGetSymbolAddress((void**)&bigA,  g_bigA);
    cudaGetSymbolAddress((void**)&bigB,  g_bigB);
    cudaGetSymbolAddress((void**)&psum,  g_psum);
    cudaGetSymbolAddress((void**)&psq,   g_psq);
    cudaGetSymbolAddress((void**)&scale, g_scale);
    cudaGetSymbolAddress((void**)&shift, g_shift);
    cudaGetSymbolAddress((void**)&wsk,   g_wskip);
    cudaGetSymbolAddress((void**)&db,    g_dbias);
    cudaGetSymbolAddress((void**)&fcw2,  g_fcw2);
    cudaGetSymbolAddress((void**)&fcb2,  g_fcb2);

    dim3 gN(NODE_CH, 4), gB(BIG_CH, 4);

    // mlp1 (node level)
    gemm_k<0,false,true,true,false,false><<<gN,64>>>(inputs,0,0, m1w1, m1b1, 0,0, 0,0,0, nodeA, 0,0);
    gemm_k<0,false,true,true,true ,false><<<gN,64>>>(nodeA ,0,0, m1w2, m1b2, 0,0, 0,0,0, nodeB, psum, psq);
    finalize_bn<<<1,256>>>(psum,psq,NODE_CH,m1g,m1be,1.f/NODE_M, scale+0, shift+0);

    // P/Q = BN1(x) @ mlp2_w1 halves (bias b1 folded into P)
    gemm_k<0,true ,true ,false,false,false><<<gN,64>>>(nodeB,0,0, m2w1,       m2b1, scale+0, shift+0, 0,0,0, P, 0,0);
    gemm_k<0,true ,false,false,false,false><<<gN,64>>>(nodeB,0,0, m2w1+65536, 0,    scale+0, shift+0, 0,0,0, Q, 0,0);

    // mlp2 layer2 (big): h2pre = ELU( ELU(P[s]+Q[r]) @ w2 + b2 ), stats2
    gemm_k<1,false,true ,true ,true ,false><<<gB,64>>>(0, P, Q, m2w2, m2b2, 0,0, 0,0,0, bigA, psum, psq);
    finalize_bn<<<1,256>>>(psum,psq,BIG_CH,m2g,m2be,1.f/BIG_M, scale+256, shift+256);

    // fold BN2 into mlp4 skip path
    fold_skip_k<<<256,256>>>(m4w1, scale+256, wsk);
    fold_dbias_k<<<1,256>>>(m4w1, m4b1, shift+256, db);

    // edge2node (BN2 applied analytically)
    edge2node_k<<<2048,256>>>(bigA, scale+256, shift+256, inc);

    // mlp3 (node level)
    gemm_k<0,false,true,true,false,false><<<gN,64>>>(inc  ,0,0, m3w1, m3b1, 0,0, 0,0,0, nodeC, 0,0);
    gemm_k<0,false,true,true,true ,false><<<gN,64>>>(nodeC,0,0, m3w2, m3b2, 0,0, 0,0,0, nodeD, psum, psq);
    finalize_bn<<<1,256>>>(psum,psq,NODE_CH,m3g,m3be,1.f/NODE_M, scale+512, shift+512);

    // S/R = BN3(x3) @ mlp4_w1 first two row-blocks
    gemm_k<0,true,false,false,false,false><<<gN,64>>>(nodeD,0,0, m4w1,       0, scale+512, shift+512, 0,0,0, S, 0,0);
    gemm_k<0,true,false,false,false,false><<<gN,64>>>(nodeD,0,0, m4w1+65536, 0, scale+512, shift+512, 0,0,0, R, 0,0);

    // mlp4 layer1 (big): t = ELU( h2pre @ wsk + S[s] + R[r] + dbias )
    gemm_k<0,false,false,true ,false,true ><<<gB,64>>>(bigA,0,0, wsk, 0, 0,0, S, R, db, bigB, 0,0);
    // mlp4 layer2 (big): h4pre = ELU( t @ w2 + b2 ), stats4
    gemm_k<0,false,true ,true ,true ,false><<<gB,64>>>(bigB,0,0, m4w2, m4b2, 0,0, 0,0,0, bigA, psum, psq);
    finalize_bn<<<1,256>>>(psum,psq,BIG_CH,m4g,m4be,1.f/BIG_M, scale+768, shift+768);

    // fold BN4 into fc, project
    fold_fc_k<<<1,256>>>(fcw, fcb, scale+768, shift+768, fcw2, fcb2);
    final_out_k<<<BIG_M/8,256>>>(bigA, fcw2, fcb2, out);
}